// round 10
// baseline (speedup 1.0000x reference)
#include <cuda_runtime.h>

// 9x9 zero-padded box filter, 128 independent 512x512 fp32 images.
// Warp-autonomous full-amortization version: CTA = 512-wide x 64-row band
// (minimum-traffic geometry), but each of the 4 warps owns a private
// 128-column strip. NO shared memory, NO barriers. Horizontal halo comes
// from __shfl within the warp; at strip edges lanes 0/31 keep a second
// vertical accumulator for the halo float4-group, fed by predicated loads
// (L1/L2 hits: the adjacent warp streams the same lines concurrently).

#define W   512
#define H   512
#define TH  64                  // rows per CTA band
#define NT  128
#define W4  (W / 4)             // 128 float4 groups per row

__global__ __launch_bounds__(NT, 7)
void box9_kernel(const float* __restrict__ xin, float* __restrict__ outp) {
    const int t    = threadIdx.x;
    const int lane = t & 31;
    const int g    = t;                       // own float4 group 0..127
    const int y0   = blockIdx.x * TH;
    const size_t imgoff = (size_t)blockIdx.y * (W * H);
    const float4* __restrict__ base  = reinterpret_cast<const float4*>(xin + imgoff);
    float4* __restrict__       obase = reinterpret_cast<float4*>(outp + imgoff);

    const float4 z4 = make_float4(0.f, 0.f, 0.f, 0.f);

    // halo group: lane 0 covers g-1, lane 31 covers g+1, others none.
    int gh = g;
    bool hv = false;
    if (lane == 0)       { gh = g - 1; hv = (g > 0); }
    else if (lane == 31) { gh = g + 1; hv = (g < W4 - 1); }

    // ---- prologue: vertical sums over input rows [y0-5, y0+3] ----
    float4 vs = z4, vsh = z4;
    #pragma unroll
    for (int i = -5; i <= 3; i++) {
        int r = y0 + i;
        if ((unsigned)r < (unsigned)H) {
            float4 v = base[r * W4 + g];
            vs.x += v.x; vs.y += v.y; vs.z += v.z; vs.w += v.w;
            if (hv) {
                float4 h = base[r * W4 + gh];
                vsh.x += h.x; vsh.y += h.y; vsh.z += h.z; vsh.w += h.w;
            }
        }
    }

    // prefetch for first iteration (rows y0, y0+1): n = x[y+4], o = x[y-5]
    float4 n0 = z4, o0 = z4, n1 = z4, o1 = z4;
    float4 hn0 = z4, ho0 = z4, hn1 = z4, ho1 = z4;
    { int r;
      r = y0 + 4; if ((unsigned)r < (unsigned)H) { n0 = base[r * W4 + g]; if (hv) hn0 = base[r * W4 + gh]; }
      r = y0 - 5; if ((unsigned)r < (unsigned)H) { o0 = base[r * W4 + g]; if (hv) ho0 = base[r * W4 + gh]; }
      r = y0 + 5; if ((unsigned)r < (unsigned)H) { n1 = base[r * W4 + g]; if (hv) hn1 = base[r * W4 + gh]; }
      r = y0 - 4; if ((unsigned)r < (unsigned)H) { o1 = base[r * W4 + g]; if (hv) ho1 = base[r * W4 + gh]; }
    }

    #pragma unroll 2
    for (int k = 0; k < TH / 2; k++) {
        const int y = y0 + 2 * k;
        float4 na = n0, oa = o0, nb = n1, ob = o1;
        float4 hna = hn0, hoa = ho0, hnb = hn1, hob = ho1;

        // prefetch for next iteration (rows y+2, y+3)
        if (k + 1 < TH / 2) {
            int r;
            n0 = z4; o0 = z4; n1 = z4; o1 = z4;
            hn0 = z4; ho0 = z4; hn1 = z4; ho1 = z4;
            r = y + 6; if ((unsigned)r < (unsigned)H) { n0 = base[r * W4 + g]; if (hv) hn0 = base[r * W4 + gh]; }
            r = y - 3; if ((unsigned)r < (unsigned)H) { o0 = base[r * W4 + g]; if (hv) ho0 = base[r * W4 + gh]; }
            r = y + 7; if ((unsigned)r < (unsigned)H) { n1 = base[r * W4 + g]; if (hv) hn1 = base[r * W4 + gh]; }
            r = y - 2; if ((unsigned)r < (unsigned)H) { o1 = base[r * W4 + g]; if (hv) ho1 = base[r * W4 + gh]; }
        }

        #pragma unroll
        for (int rr = 0; rr < 2; rr++) {
            // vertical slide for this row
            if (rr == 0) {
                vs.x  += na.x - oa.x;   vs.y  += na.y - oa.y;
                vs.z  += na.z - oa.z;   vs.w  += na.w - oa.w;
                vsh.x += hna.x - hoa.x; vsh.y += hna.y - hoa.y;
                vsh.z += hna.z - hoa.z; vsh.w += hna.w - hoa.w;
            } else {
                vs.x  += nb.x - ob.x;   vs.y  += nb.y - ob.y;
                vs.z  += nb.z - ob.z;   vs.w  += nb.w - ob.w;
                vsh.x += hnb.x - hob.x; vsh.y += hnb.y - hob.y;
                vsh.z += hnb.z - hob.z; vsh.w += hnb.w - hob.w;
            }

            // neighbor vsums via warp shuffle; strip edges use vsh
            float4 L, R;
            L.x = __shfl_up_sync(0xffffffffu, vs.x, 1);
            L.y = __shfl_up_sync(0xffffffffu, vs.y, 1);
            L.z = __shfl_up_sync(0xffffffffu, vs.z, 1);
            L.w = __shfl_up_sync(0xffffffffu, vs.w, 1);
            R.x = __shfl_down_sync(0xffffffffu, vs.x, 1);
            R.y = __shfl_down_sync(0xffffffffu, vs.y, 1);
            R.z = __shfl_down_sync(0xffffffffu, vs.z, 1);
            R.w = __shfl_down_sync(0xffffffffu, vs.w, 1);
            if (lane == 0)  L = vsh;   // vsh==0 at image left edge (hv false)
            if (lane == 31) R = vsh;   // vsh==0 at image right edge

            // horizontal 9-sum sliding over 4 output columns
            float sb = (vs.x + vs.y) + (vs.z + vs.w);
            float sa = (L.x + L.y) + (L.z + L.w);
            float h0 = sa + sb + R.x;
            float h1 = h0 - L.x + R.y;
            float h2 = h1 - L.y + R.z;
            float h3 = h2 - L.z + R.w;
            __stcs(&obase[(y + rr) * W4 + g], make_float4(h0, h1, h2, h3));
        }
    }
}

extern "C" void kernel_launch(void* const* d_in, const int* in_sizes, int n_in,
                              void* d_out, int out_size) {
    const float* x = (const float*)d_in[0];
    float* out = (float*)d_out;
    int nimg = in_sizes[0] / (W * H);     // 128
    dim3 grid(H / TH, nimg);              // (8, 128) = 1024 CTAs
    box9_kernel<<<grid, NT>>>(x, out);
}

// round 11
// speedup vs baseline: 1.5591x; 1.5591x over previous
#include <cuda_runtime.h>

// 9x9 zero-padded box filter, 128 independent 512x512 fp32 images.
// Full-width row pipeline (R7 champion structure): CTA = 512-wide x 64-row
// band, vertical 9-sum sliding in registers, horizontal 9-sum via smem
// ring, streaming output stores.
// R11: prologue split by __syncthreads() every 3 rows so ptxas cannot
// front-batch all 13 prologue/prefetch LDGs (MLP_p1 13 -> ~5), reducing
// cross-CTA L1tex-queue contention / CTA completion spread (B300 spread
// model), which capped DRAM busy at 72%.

#define W   512
#define H   512
#define TH  64                  // rows per CTA band
#define NT  128                 // one thread per float4 column group (512/4)
#define W4  (W / 4)             // 128

__global__ __launch_bounds__(NT) void box9_kernel(const float* __restrict__ xin,
                                                  float* __restrict__ outp) {
    // 4 row-buffers (2 rows in flight per barrier, alternating pairs).
    // Slot s: index t+1 is own column group; 0 and 129 are the zero halo.
    __shared__ __align__(16) float4 buf[4][132];

    const int t  = threadIdx.x;
    const int y0 = blockIdx.x * TH;
    const size_t imgoff = (size_t)blockIdx.y * (W * H);
    const float4* __restrict__ base  = reinterpret_cast<const float4*>(xin + imgoff);
    float4* __restrict__       obase = reinterpret_cast<float4*>(outp + imgoff);

    const float4 z4 = make_float4(0.f, 0.f, 0.f, 0.f);
    if (t < 4) {
        buf[t][0]   = z4;
        buf[t][129] = z4;
    }

    // ---- prologue: vs = sum of input rows [y0-5, y0+3] (zeros outside) ----
    // Invariant before the slide at output row y: vs = sum rows [y-5, y+3].
    // Split into 3-row chunks separated by barriers: ptxas cannot hoist LDG
    // across BAR.SYNC, so the front-of-kernel LDG clump stays small.
    float4 vs = z4;
    #pragma unroll
    for (int i = -5; i <= -3; i++) {
        int r = y0 + i;
        if ((unsigned)r < (unsigned)H) {
            float4 v = base[r * W4 + t];
            vs.x += v.x; vs.y += v.y; vs.z += v.z; vs.w += v.w;
        }
    }
    __syncthreads();
    #pragma unroll
    for (int i = -2; i <= 0; i++) {
        int r = y0 + i;
        if ((unsigned)r < (unsigned)H) {
            float4 v = base[r * W4 + t];
            vs.x += v.x; vs.y += v.y; vs.z += v.z; vs.w += v.w;
        }
    }
    __syncthreads();
    #pragma unroll
    for (int i = 1; i <= 3; i++) {
        int r = y0 + i;
        if ((unsigned)r < (unsigned)H) {
            float4 v = base[r * W4 + t];
            vs.x += v.x; vs.y += v.y; vs.z += v.z; vs.w += v.w;
        }
    }

    // prefetch rows for the first iteration (output rows y0, y0+1):
    //   n = x[y+4], o = x[y-5]
    float4 n0 = z4, o0 = z4, n1 = z4, o1 = z4;
    { int r;
      r = y0 + 4; if ((unsigned)r < (unsigned)H) n0 = base[r * W4 + t];
      r = y0 - 5; if ((unsigned)r < (unsigned)H) o0 = base[r * W4 + t];
      r = y0 + 5; if ((unsigned)r < (unsigned)H) n1 = base[r * W4 + t];
      r = y0 - 4; if ((unsigned)r < (unsigned)H) o1 = base[r * W4 + t];
    }

    #pragma unroll 2
    for (int k = 0; k < TH / 2; k++) {
        const int y = y0 + 2 * k;
        float4 na = n0, oa = o0, nb = n1, ob = o1;

        // prefetch rows for next iteration (output rows y+2, y+3)
        if (k + 1 < TH / 2) {
            int r;
            n0 = z4; o0 = z4; n1 = z4; o1 = z4;
            r = y + 6; if ((unsigned)r < (unsigned)H) n0 = base[r * W4 + t];
            r = y - 3; if ((unsigned)r < (unsigned)H) o0 = base[r * W4 + t];
            r = y + 7; if ((unsigned)r < (unsigned)H) n1 = base[r * W4 + t];
            r = y - 2; if ((unsigned)r < (unsigned)H) o1 = base[r * W4 + t];
        }

        // vertical slide, two rows
        vs.x += na.x - oa.x; vs.y += na.y - oa.y;
        vs.z += na.z - oa.z; vs.w += na.w - oa.w;
        float4 vs0 = vs;
        buf[(2 * k) & 3][t + 1] = vs0;

        vs.x += nb.x - ob.x; vs.y += nb.y - ob.y;
        vs.z += nb.z - ob.z; vs.w += nb.w - ob.w;
        float4 vs1 = vs;
        buf[(2 * k + 1) & 3][t + 1] = vs1;

        __syncthreads();

        // horizontal slide, row y (streaming store: keep L2 for input)
        {
            float4 a = buf[(2 * k) & 3][t];
            float4 c = buf[(2 * k) & 3][t + 2];
            float sb = (vs0.x + vs0.y) + (vs0.z + vs0.w);
            float sa = (a.x + a.y) + (a.z + a.w);
            float h0 = sa + sb + c.x;
            float h1 = h0 - a.x + c.y;
            float h2 = h1 - a.y + c.z;
            float h3 = h2 - a.z + c.w;
            __stcs(&obase[y * W4 + t], make_float4(h0, h1, h2, h3));
        }
        // horizontal slide, row y+1
        {
            float4 a = buf[(2 * k + 1) & 3][t];
            float4 c = buf[(2 * k + 1) & 3][t + 2];
            float sb = (vs1.x + vs1.y) + (vs1.z + vs1.w);
            float sa = (a.x + a.y) + (a.z + a.w);
            float h0 = sa + sb + c.x;
            float h1 = h0 - a.x + c.y;
            float h2 = h1 - a.y + c.z;
            float h3 = h2 - a.z + c.w;
            __stcs(&obase[(y + 1) * W4 + t], make_float4(h0, h1, h2, h3));
        }
    }
}

extern "C" void kernel_launch(void* const* d_in, const int* in_sizes, int n_in,
                              void* d_out, int out_size) {
    const float* x = (const float*)d_in[0];
    float* out = (float*)d_out;
    int nimg = in_sizes[0] / (W * H);     // 128
    dim3 grid(H / TH, nimg);              // (8, 128) = 1024 CTAs
    box9_kernel<<<grid, NT>>>(x, out);
}